// round 4
// baseline (speedup 1.0000x reference)
#include <cuda_runtime.h>
#include <cuda_bf16.h>
#include <cstdint>

// ============================================================================
// Problem dims
// ============================================================================
#define B_DIM 4
#define S_DIM 4096
#define D_DIM 1024
#define M_TOT (B_DIM * S_DIM)   // 16384
#define NCH 32
#define CHL (S_DIM / NCH)       // 128

// ============================================================================
// Device scratch (allocation-free rule -> static __device__ arrays)
// ============================================================================
__device__ __nv_bfloat16 g_xh[M_TOT * D_DIM];            // 32 MB
__device__ __nv_bfloat16 g_xl[M_TOT * D_DIM];            // 32 MB
// [0]=Wg_hi [1]=Wg_lo [2]=Wv_hi [3]=Wv_lo [4]=Wd_hi [5]=Wd_lo
__device__ __nv_bfloat16 g_wsp[6][D_DIM * D_DIM];        // 12 MB
__device__ float g_A [M_TOT * D_DIM];                    // 64 MB (decay a)
__device__ float g_XS[M_TOT * D_DIM];                    // 64 MB (x_scan)
__device__ float g_Aprod[NCH * B_DIM * D_DIM];
__device__ float g_Hend [NCH * B_DIM * D_DIM];
__device__ float g_Hin  [NCH * B_DIM * D_DIM];

// ============================================================================
// PTX helpers (sm_80-level features only: mma.sync + cp.async)
// ============================================================================
__device__ __forceinline__ uint32_t smem_to_u32(const void* p) {
    uint32_t a;
    asm("{ .reg .u64 t; cvta.to.shared.u64 t, %1; cvt.u32.u64 %0, t; }"
        : "=r"(a) : "l"(p));
    return a;
}

__device__ __forceinline__ void cp8(uint32_t dst, const void* src) {
    asm volatile("cp.async.ca.shared.global [%0], [%1], 8;"
                 :: "r"(dst), "l"(src) : "memory");
}
__device__ __forceinline__ void cp_commit() {
    asm volatile("cp.async.commit_group;" ::: "memory");
}

// D += A * B  (m16n8k16, bf16 in, f32 accum, A row-major, B col-major)
__device__ __forceinline__ void mma16816(float* c, const uint32_t* a, const uint32_t* b) {
    asm volatile(
        "mma.sync.aligned.m16n8k16.row.col.f32.bf16.bf16.f32 "
        "{%0,%1,%2,%3}, {%4,%5,%6,%7}, {%8,%9}, {%0,%1,%2,%3};"
        : "+f"(c[0]), "+f"(c[1]), "+f"(c[2]), "+f"(c[3])
        : "r"(a[0]), "r"(a[1]), "r"(a[2]), "r"(a[3]), "r"(b[0]), "r"(b[1]));
}

// ============================================================================
// Kernel 1: split x (fp32) into bf16 hi/lo
// ============================================================================
__global__ void split_x_kernel(const float* __restrict__ x) {
    int i = blockIdx.x * blockDim.x + threadIdx.x;   // float4 index
    float4 v = ((const float4*)x)[i];
    union { __nv_bfloat16 h[4]; uint2 u; } hi, lo;
    hi.h[0] = __float2bfloat16(v.x); lo.h[0] = __float2bfloat16(v.x - __bfloat162float(hi.h[0]));
    hi.h[1] = __float2bfloat16(v.y); lo.h[1] = __float2bfloat16(v.y - __bfloat162float(hi.h[1]));
    hi.h[2] = __float2bfloat16(v.z); lo.h[2] = __float2bfloat16(v.z - __bfloat162float(hi.h[2]));
    hi.h[3] = __float2bfloat16(v.w); lo.h[3] = __float2bfloat16(v.w - __bfloat162float(hi.h[3]));
    ((uint2*)g_xh)[i] = hi.u;
    ((uint2*)g_xl)[i] = lo.u;
}

// ============================================================================
// Kernel 2: split the 3 weight matrices into bf16 hi/lo
// ============================================================================
__global__ void split_w_kernel(const float* __restrict__ Wg,
                               const float* __restrict__ Wv,
                               const float* __restrict__ Wd) {
    int gid = blockIdx.x * blockDim.x + threadIdx.x;   // float4 index, 3*262144
    int which = gid >> 18;
    int r = gid & ((1 << 18) - 1);
    const float* src = (which == 0) ? Wg : (which == 1) ? Wv : Wd;
    float4 v = ((const float4*)src)[r];
    union { __nv_bfloat16 h[4]; uint2 u; } hi, lo;
    hi.h[0] = __float2bfloat16(v.x); lo.h[0] = __float2bfloat16(v.x - __bfloat162float(hi.h[0]));
    hi.h[1] = __float2bfloat16(v.y); lo.h[1] = __float2bfloat16(v.y - __bfloat162float(hi.h[1]));
    hi.h[2] = __float2bfloat16(v.z); lo.h[2] = __float2bfloat16(v.z - __bfloat162float(hi.h[2]));
    hi.h[3] = __float2bfloat16(v.w); lo.h[3] = __float2bfloat16(v.w - __bfloat162float(hi.h[3]));
    ((uint2*)g_wsp[which * 2    ])[r] = hi.u;
    ((uint2*)g_wsp[which * 2 + 1])[r] = lo.u;
}

// ============================================================================
// Kernel 3: fused triple GEMM (split-bf16, mma.sync) + gate epilogue
//   CTA tile: M=128, N=64, K looped in BK=64. 8 warps = 4(M) x 2(N).
//   Warp tile 32x32 per output; 3 outputs (g,v,d) in registers.
//   Double-buffered cp.async staging; padded smem rows (144 B) ->
//   conflict-free fragment LDS.
// ============================================================================
#define BK 64
#define KCHUNKS 16
#define TSTRIDE_B 144                       // 64 bf16 + 8 pad, in bytes
#define XT_BYTES (128 * TSTRIDE_B)          // 18432
#define WT_BYTES (64 * TSTRIDE_B)           // 9216
#define STAGE_BYTES (2 * XT_BYTES + 6 * WT_BYTES)   // 92160
#define GEMM_SMEM (2 * STAGE_BYTES)                 // 184320

__device__ __forceinline__ void stage_load(uint32_t sbase, int m0, int n0,
                                           int k0, int tid) {
    // x_hi / x_lo tiles: 128 rows x 64 bf16 (16 uint2 per row)
    #pragma unroll
    for (int it = 0; it < 8; it++) {
        int idx = tid + it * 256;            // 0..2047
        int row = idx >> 4, c8 = idx & 15;
        uint32_t d = sbase + row * TSTRIDE_B + c8 * 8;
        const size_t go = (size_t)(m0 + row) * 1024 + k0 + c8 * 4;
        cp8(d,             g_xh + go);
        cp8(d + XT_BYTES,  g_xl + go);
    }
    // 6 W tiles: 64 rows x 64 bf16 each
    #pragma unroll
    for (int w = 0; w < 6; w++) {
        uint32_t wb = sbase + 2 * XT_BYTES + w * WT_BYTES;
        #pragma unroll
        for (int it = 0; it < 4; it++) {
            int idx = tid + it * 256;        // 0..1023
            int row = idx >> 4, c8 = idx & 15;
            cp8(wb + row * TSTRIDE_B + c8 * 8,
                g_wsp[w] + (size_t)(n0 + row) * 1024 + k0 + c8 * 4);
        }
    }
}

__global__ __launch_bounds__(256, 1)
void gemm3_kernel(const float* __restrict__ bgp,
                  const float* __restrict__ bvp,
                  const float* __restrict__ bdp) {
    extern __shared__ char smem[];
    const uint32_t smem_u = smem_to_u32(smem);
    const int tid  = threadIdx.x;
    const int wid  = tid >> 5;
    const int lane = tid & 31;
    const int gid  = lane >> 2;            // 0..7
    const int tig  = lane & 3;             // 0..3
    const int warp_m = wid >> 1;           // 0..3
    const int warp_n = wid & 1;            // 0..1
    const int m0 = blockIdx.x * 128;
    const int n0 = blockIdx.y * 64;

    float acc[3][2][4][4];                 // [out][mt][nt][frag]
    #pragma unroll
    for (int w = 0; w < 3; w++)
        #pragma unroll
        for (int mt = 0; mt < 2; mt++)
            #pragma unroll
            for (int nt = 0; nt < 4; nt++)
                #pragma unroll
                for (int f = 0; f < 4; f++) acc[w][mt][nt][f] = 0.f;

    stage_load(smem_u, m0, n0, 0, tid);
    cp_commit();

    for (int ch = 0; ch < KCHUNKS; ch++) {
        const int buf = ch & 1;
        if (ch + 1 < KCHUNKS) {
            stage_load(smem_u + (buf ^ 1) * STAGE_BYTES, m0, n0, (ch + 1) * BK, tid);
            cp_commit();
            asm volatile("cp.async.wait_group 1;" ::: "memory");
        } else {
            asm volatile("cp.async.wait_group 0;" ::: "memory");
        }
        __syncthreads();

        const char* sb = smem + buf * STAGE_BYTES;
        #pragma unroll
        for (int ks = 0; ks < 4; ks++) {
            // ---- A fragments (x_hi, x_lo), 2 m-tiles
            uint32_t ah[2][4], al[2][4];
            #pragma unroll
            for (int mt = 0; mt < 2; mt++) {
                const char* ab = sb + (warp_m * 32 + mt * 16 + gid) * TSTRIDE_B
                                    + ks * 32 + tig * 4;
                ah[mt][0] = *(const uint32_t*)(ab);
                ah[mt][1] = *(const uint32_t*)(ab + 8 * TSTRIDE_B);
                ah[mt][2] = *(const uint32_t*)(ab + 16);
                ah[mt][3] = *(const uint32_t*)(ab + 8 * TSTRIDE_B + 16);
                al[mt][0] = *(const uint32_t*)(ab + XT_BYTES);
                al[mt][1] = *(const uint32_t*)(ab + XT_BYTES + 8 * TSTRIDE_B);
                al[mt][2] = *(const uint32_t*)(ab + XT_BYTES + 16);
                al[mt][3] = *(const uint32_t*)(ab + XT_BYTES + 8 * TSTRIDE_B + 16);
            }
            // ---- per output matrix: B fragments + 3 split products
            #pragma unroll
            for (int w = 0; w < 3; w++) {
                uint32_t bh[4][2], bl[4][2];
                const char* wb = sb + 2 * XT_BYTES + (2 * w) * WT_BYTES;
                #pragma unroll
                for (int nt = 0; nt < 4; nt++) {
                    const char* bb = wb + (warp_n * 32 + nt * 8 + gid) * TSTRIDE_B
                                        + ks * 32 + tig * 4;
                    bh[nt][0] = *(const uint32_t*)(bb);
                    bh[nt][1] = *(const uint32_t*)(bb + 16);
                    bl[nt][0] = *(const uint32_t*)(bb + WT_BYTES);
                    bl[nt][1] = *(const uint32_t*)(bb + WT_BYTES + 16);
                }
                #pragma unroll
                for (int mt = 0; mt < 2; mt++)
                    #pragma unroll
                    for (int nt = 0; nt < 4; nt++) {
                        mma16816(acc[w][mt][nt], ah[mt], bh[nt]);  // hi*hi
                        mma16816(acc[w][mt][nt], ah[mt], bl[nt]);  // hi*lo
                        mma16816(acc[w][mt][nt], al[mt], bh[nt]);  // lo*hi
                    }
            }
        }
        __syncthreads();
    }

    // ---- fused gate epilogue: a = 0.001 + 0.998*sigmoid(d); xs = sigmoid(g)*tanh(v)
    #pragma unroll
    for (int mt = 0; mt < 2; mt++) {
        #pragma unroll
        for (int half = 0; half < 2; half++) {
            const int m = m0 + warp_m * 32 + mt * 16 + gid + half * 8;
            float* Ar = g_A  + (size_t)m * 1024;
            float* Xr = g_XS + (size_t)m * 1024;
            #pragma unroll
            for (int nt = 0; nt < 4; nt++) {
                const int n = n0 + warp_n * 32 + nt * 8 + tig * 2;
                float2 av, xv;
                #pragma unroll
                for (int j = 0; j < 2; j++) {
                    const int f = half * 2 + j;
                    float gg = acc[0][mt][nt][f] + __ldg(bgp + n + j);
                    float vv = acc[1][mt][nt][f] + __ldg(bvp + n + j);
                    float dd = acc[2][mt][nt][f] + __ldg(bdp + n + j);
                    float sg = 1.f / (1.f + __expf(-gg));
                    float sd = 1.f / (1.f + __expf(-dd));
                    float a  = 0.001f + 0.998f * sd;
                    float xs = sg * tanhf(vv);
                    if (j == 0) { av.x = a; xv.x = xs; }
                    else        { av.y = a; xv.y = xs; }
                }
                *(float2*)(Ar + n) = av;
                *(float2*)(Xr + n) = xv;
            }
        }
    }
}

// ============================================================================
// Kernels 4-6: chunked causal scan  h_t = a_t * h_{t-1} + xs_t
// ============================================================================
__global__ void scan_phase1(float* __restrict__ out) {
    int c = blockIdx.x * 256 + threadIdx.x;      // channel (b*1024 + d)
    int chunk = blockIdx.y;
    size_t off = ((size_t)(c >> 10) * S_DIM + (size_t)chunk * CHL) * 1024 + (c & 1023);
    float h = 0.f, p = 1.f;
    #pragma unroll 8
    for (int t = 0; t < CHL; t++) {
        float a  = g_A[off];
        float xs = g_XS[off];
        h = fmaf(a, h, xs);
        p *= a;
        out[off] = h;
        off += 1024;
    }
    g_Aprod[chunk * 4096 + c] = p;
    g_Hend [chunk * 4096 + c] = h;
}

__global__ void scan_phase2() {
    int c = blockIdx.x * 256 + threadIdx.x;
    float carry = 0.f;
    #pragma unroll
    for (int ch = 0; ch < NCH; ch++) {
        g_Hin[ch * 4096 + c] = carry;
        carry = fmaf(g_Aprod[ch * 4096 + c], carry, g_Hend[ch * 4096 + c]);
    }
}

__global__ void scan_phase3(float* __restrict__ out) {
    int c = blockIdx.x * 256 + threadIdx.x;
    int chunk = blockIdx.y + 1;                  // 1..31
    float hin = g_Hin[chunk * 4096 + c];
    size_t off = ((size_t)(c >> 10) * S_DIM + (size_t)chunk * CHL) * 1024 + (c & 1023);
    float p = 1.f;
    #pragma unroll 8
    for (int t = 0; t < CHL; t++) {
        p *= g_A[off];
        out[off] = fmaf(hin, p, out[off]);
        off += 1024;
    }
}

// ============================================================================
// Launch
// ============================================================================
extern "C" void kernel_launch(void* const* d_in, const int* in_sizes, int n_in,
                              void* d_out, int out_size) {
    const float* x  = (const float*)d_in[0];
    const float* Wg = (const float*)d_in[1];
    const float* bg = (const float*)d_in[2];
    const float* Wv = (const float*)d_in[3];
    const float* bv = (const float*)d_in[4];
    const float* Wd = (const float*)d_in[5];
    const float* bd = (const float*)d_in[6];
    float* out = (float*)d_out;
    (void)in_sizes; (void)n_in; (void)out_size;

    split_x_kernel<<<M_TOT * D_DIM / 4 / 256, 256>>>(x);
    split_w_kernel<<<3 * D_DIM * D_DIM / 4 / 256, 256>>>(Wg, Wv, Wd);

    cudaFuncSetAttribute(gemm3_kernel,
                         cudaFuncAttributeMaxDynamicSharedMemorySize, GEMM_SMEM);
    gemm3_kernel<<<dim3(M_TOT / 128, D_DIM / 64), 256, GEMM_SMEM>>>(bg, bv, bd);

    scan_phase1<<<dim3(16, NCH), 256>>>(out);
    scan_phase2<<<16, 256>>>();
    scan_phase3<<<dim3(16, NCH - 1), 256>>>(out);
}

// round 6
// speedup vs baseline: 1.3170x; 1.3170x over previous
#include <cuda_runtime.h>
#include <cuda_fp16.h>
#include <cstdint>

// ============================================================================
// Problem dims
// ============================================================================
#define B_DIM 4
#define S_DIM 4096
#define D_DIM 1024
#define M_TOT (B_DIM * S_DIM)   // 16384
#define NCH 64
#define CHL (S_DIM / NCH)       // 64

// ============================================================================
// Device scratch (allocation-free rule -> static __device__ arrays)
// ============================================================================
__device__ __align__(128) __half g_xh[M_TOT * D_DIM];     // 32 MB (x as fp16)
// [0]=Wg_hi [1]=Wg_lo [2]=Wv_hi [3]=Wv_lo [4]=Wd_hi [5]=Wd_lo
__device__ __align__(128) __half g_wsp[6][D_DIM * D_DIM]; // 12 MB
__device__ float g_A [M_TOT * D_DIM];                     // 64 MB (decay a)
__device__ float g_XS[M_TOT * D_DIM];                     // 64 MB (x_scan)
__device__ float g_Aprod[NCH * B_DIM * D_DIM];
__device__ float g_Hend [NCH * B_DIM * D_DIM];
__device__ float g_Hin  [NCH * B_DIM * D_DIM];

// ============================================================================
// PTX helpers (sm_80-level features only: mma.sync + cp.async)
// ============================================================================
__device__ __forceinline__ uint32_t smem_to_u32(const void* p) {
    uint32_t a;
    asm("{ .reg .u64 t; cvta.to.shared.u64 t, %1; cvt.u32.u64 %0, t; }"
        : "=r"(a) : "l"(p));
    return a;
}

__device__ __forceinline__ void cp16(uint32_t dst, const void* src) {
    asm volatile("cp.async.cg.shared.global [%0], [%1], 16;"
                 :: "r"(dst), "l"(src) : "memory");
}
__device__ __forceinline__ void cp_commit() {
    asm volatile("cp.async.commit_group;" ::: "memory");
}

// D += A * B  (m16n8k16, fp16 in, f32 accum, A row-major, B col-major)
__device__ __forceinline__ void mma16816(float* c, const uint32_t* a, const uint32_t* b) {
    asm volatile(
        "mma.sync.aligned.m16n8k16.row.col.f32.f16.f16.f32 "
        "{%0,%1,%2,%3}, {%4,%5,%6,%7}, {%8,%9}, {%0,%1,%2,%3};"
        : "+f"(c[0]), "+f"(c[1]), "+f"(c[2]), "+f"(c[3])
        : "r"(a[0]), "r"(a[1]), "r"(a[2]), "r"(a[3]), "r"(b[0]), "r"(b[1]));
}

// ============================================================================
// Kernel 1: x (fp32) -> fp16
// ============================================================================
__global__ void split_x_kernel(const float* __restrict__ x) {
    int i = blockIdx.x * blockDim.x + threadIdx.x;   // float4 index
    float4 v = ((const float4*)x)[i];
    union { __half h[4]; uint2 u; } hi;
    hi.h[0] = __float2half_rn(v.x);
    hi.h[1] = __float2half_rn(v.y);
    hi.h[2] = __float2half_rn(v.z);
    hi.h[3] = __float2half_rn(v.w);
    ((uint2*)g_xh)[i] = hi.u;
}

// ============================================================================
// Kernel 2: split the 3 weight matrices into fp16 hi/lo
// ============================================================================
__global__ void split_w_kernel(const float* __restrict__ Wg,
                               const float* __restrict__ Wv,
                               const float* __restrict__ Wd) {
    int gid = blockIdx.x * blockDim.x + threadIdx.x;   // float4 index, 3*262144
    int which = gid >> 18;
    int r = gid & ((1 << 18) - 1);
    const float* src = (which == 0) ? Wg : (which == 1) ? Wv : Wd;
    float4 v = ((const float4*)src)[r];
    union { __half h[4]; uint2 u; } hi, lo;
    hi.h[0] = __float2half_rn(v.x); lo.h[0] = __float2half_rn(v.x - __half2float(hi.h[0]));
    hi.h[1] = __float2half_rn(v.y); lo.h[1] = __float2half_rn(v.y - __half2float(hi.h[1]));
    hi.h[2] = __float2half_rn(v.z); lo.h[2] = __float2half_rn(v.z - __half2float(hi.h[2]));
    hi.h[3] = __float2half_rn(v.w); lo.h[3] = __float2half_rn(v.w - __half2float(hi.h[3]));
    ((uint2*)g_wsp[which * 2    ])[r] = hi.u;
    ((uint2*)g_wsp[which * 2 + 1])[r] = lo.u;
}

// ============================================================================
// Kernel 3: fused triple GEMM (split-fp16, 2 products) + gate epilogue
//   CTA tile: M=128, N=64, K looped in BK=64. 8 warps = 4(M) x 2(N).
//   y = x_fp16 @ (Wh + Wl)^T : per output, 2 MMA products.
//   Double-buffered 16B cp.async staging; padded smem rows (144 B) ->
//   conflict-free fragment LDS.
// ============================================================================
#define BK 64
#define KCHUNKS 16
#define TSTRIDE_B 144                       // 64 fp16 + 8 pad, in bytes
#define XT_BYTES (128 * TSTRIDE_B)          // 18432
#define WT_BYTES (64 * TSTRIDE_B)           // 9216
#define STAGE_BYTES (XT_BYTES + 6 * WT_BYTES)       // 73728
#define GEMM_SMEM (2 * STAGE_BYTES)                 // 147456

__device__ __forceinline__ void stage_load(uint32_t sbase, int m0, int n0,
                                           int k0, int tid) {
    // x tile: 128 rows x 64 fp16 (8 x 16B per row)
    #pragma unroll
    for (int it = 0; it < 4; it++) {
        int idx = tid + it * 256;            // 0..1023
        int row = idx >> 3, c16 = idx & 7;
        cp16(sbase + row * TSTRIDE_B + c16 * 16,
             g_xh + (size_t)(m0 + row) * 1024 + k0 + c16 * 8);
    }
    // 6 W tiles: 64 rows x 64 fp16 each
    #pragma unroll
    for (int w = 0; w < 6; w++) {
        uint32_t wb = sbase + XT_BYTES + w * WT_BYTES;
        #pragma unroll
        for (int it = 0; it < 2; it++) {
            int idx = tid + it * 256;        // 0..511
            int row = idx >> 3, c16 = idx & 7;
            cp16(wb + row * TSTRIDE_B + c16 * 16,
                 g_wsp[w] + (size_t)(n0 + row) * 1024 + k0 + c16 * 8);
        }
    }
}

__global__ __launch_bounds__(256, 1)
void gemm3_kernel(const float* __restrict__ bgp,
                  const float* __restrict__ bvp,
                  const float* __restrict__ bdp) {
    extern __shared__ char smem[];
    const uint32_t smem_u = smem_to_u32(smem);
    const int tid  = threadIdx.x;
    const int wid  = tid >> 5;
    const int lane = tid & 31;
    const int gid  = lane >> 2;            // 0..7
    const int tig  = lane & 3;             // 0..3
    const int warp_m = wid >> 1;           // 0..3
    const int warp_n = wid & 1;            // 0..1
    const int m0 = blockIdx.x * 128;
    const int n0 = blockIdx.y * 64;

    float acc[3][2][4][4];                 // [out][mt][nt][frag]
    #pragma unroll
    for (int w = 0; w < 3; w++)
        #pragma unroll
        for (int mt = 0; mt < 2; mt++)
            #pragma unroll
            for (int nt = 0; nt < 4; nt++)
                #pragma unroll
                for (int f = 0; f < 4; f++) acc[w][mt][nt][f] = 0.f;

    stage_load(smem_u, m0, n0, 0, tid);
    cp_commit();

    for (int ch = 0; ch < KCHUNKS; ch++) {
        const int buf = ch & 1;
        if (ch + 1 < KCHUNKS) {
            stage_load(smem_u + (buf ^ 1) * STAGE_BYTES, m0, n0, (ch + 1) * BK, tid);
            cp_commit();
            asm volatile("cp.async.wait_group 1;" ::: "memory");
        } else {
            asm volatile("cp.async.wait_group 0;" ::: "memory");
        }
        __syncthreads();

        const char* sb = smem + buf * STAGE_BYTES;
        #pragma unroll
        for (int ks = 0; ks < 4; ks++) {
            // ---- A fragments (x fp16), 2 m-tiles
            uint32_t ah[2][4];
            #pragma unroll
            for (int mt = 0; mt < 2; mt++) {
                const char* ab = sb + (warp_m * 32 + mt * 16 + gid) * TSTRIDE_B
                                    + ks * 32 + tig * 4;
                ah[mt][0] = *(const uint32_t*)(ab);
                ah[mt][1] = *(const uint32_t*)(ab + 8 * TSTRIDE_B);
                ah[mt][2] = *(const uint32_t*)(ab + 16);
                ah[mt][3] = *(const uint32_t*)(ab + 8 * TSTRIDE_B + 16);
            }
            // ---- per output matrix: Wh/Wl fragments + 2 products
            #pragma unroll
            for (int w = 0; w < 3; w++) {
                uint32_t bh[4][2], bl[4][2];
                const char* wbh = sb + XT_BYTES + (2 * w) * WT_BYTES;
                #pragma unroll
                for (int nt = 0; nt < 4; nt++) {
                    const char* bb = wbh + (warp_n * 32 + nt * 8 + gid) * TSTRIDE_B
                                         + ks * 32 + tig * 4;
                    bh[nt][0] = *(const uint32_t*)(bb);
                    bh[nt][1] = *(const uint32_t*)(bb + 16);
                    bl[nt][0] = *(const uint32_t*)(bb + WT_BYTES);
                    bl[nt][1] = *(const uint32_t*)(bb + WT_BYTES + 16);
                }
                #pragma unroll
                for (int mt = 0; mt < 2; mt++)
                    #pragma unroll
                    for (int nt = 0; nt < 4; nt++) {
                        mma16816(acc[w][mt][nt], ah[mt], bh[nt]);  // x * Wh
                        mma16816(acc[w][mt][nt], ah[mt], bl[nt]);  // x * Wl
                    }
            }
        }
        __syncthreads();
    }

    // ---- fused gate epilogue: a = 0.001 + 0.998*sigmoid(d); xs = sigmoid(g)*tanh(v)
    #pragma unroll
    for (int mt = 0; mt < 2; mt++) {
        #pragma unroll
        for (int half = 0; half < 2; half++) {
            const int m = m0 + warp_m * 32 + mt * 16 + gid + half * 8;
            float* Ar = g_A  + (size_t)m * 1024;
            float* Xr = g_XS + (size_t)m * 1024;
            #pragma unroll
            for (int nt = 0; nt < 4; nt++) {
                const int n = n0 + warp_n * 32 + nt * 8 + tig * 2;
                float2 av, xv;
                #pragma unroll
                for (int j = 0; j < 2; j++) {
                    const int f = half * 2 + j;
                    float gg = acc[0][mt][nt][f] + __ldg(bgp + n + j);
                    float vv = acc[1][mt][nt][f] + __ldg(bvp + n + j);
                    float dd = acc[2][mt][nt][f] + __ldg(bdp + n + j);
                    float sg = 1.f / (1.f + __expf(-gg));
                    float sd = 1.f / (1.f + __expf(-dd));
                    float a  = 0.001f + 0.998f * sd;
                    float xs = sg * tanhf(vv);
                    if (j == 0) { av.x = a; xv.x = xs; }
                    else        { av.y = a; xv.y = xs; }
                }
                *(float2*)(Ar + n) = av;
                *(float2*)(Xr + n) = xv;
            }
        }
    }
}

// ============================================================================
// Kernels 4-6: chunked causal scan  h_t = a_t * h_{t-1} + xs_t   (NCH=64)
// ============================================================================
__global__ void scan_phase1(float* __restrict__ out) {
    int c = blockIdx.x * 256 + threadIdx.x;      // channel (b*1024 + d)
    int chunk = blockIdx.y;
    size_t off = ((size_t)(c >> 10) * S_DIM + (size_t)chunk * CHL) * 1024 + (c & 1023);
    float h = 0.f, p = 1.f;
    #pragma unroll 8
    for (int t = 0; t < CHL; t++) {
        float a  = g_A[off];
        float xs = g_XS[off];
        h = fmaf(a, h, xs);
        p *= a;
        out[off] = h;
        off += 1024;
    }
    g_Aprod[chunk * 4096 + c] = p;
    g_Hend [chunk * 4096 + c] = h;
}

__global__ void scan_phase2() {
    int c = blockIdx.x * 256 + threadIdx.x;
    float carry = 0.f;
    #pragma unroll
    for (int ch = 0; ch < NCH; ch++) {
        g_Hin[ch * 4096 + c] = carry;
        carry = fmaf(g_Aprod[ch * 4096 + c], carry, g_Hend[ch * 4096 + c]);
    }
}

__global__ void scan_phase3(float* __restrict__ out) {
    int c = blockIdx.x * 256 + threadIdx.x;
    int chunk = blockIdx.y + 1;                  // 1..NCH-1
    float hin = g_Hin[chunk * 4096 + c];
    size_t off = ((size_t)(c >> 10) * S_DIM + (size_t)chunk * CHL) * 1024 + (c & 1023);
    float p = 1.f;
    #pragma unroll 8
    for (int t = 0; t < CHL; t++) {
        p *= g_A[off];
        out[off] = fmaf(hin, p, out[off]);
        off += 1024;
    }
}

// ============================================================================
// Launch
// ============================================================================
extern "C" void kernel_launch(void* const* d_in, const int* in_sizes, int n_in,
                              void* d_out, int out_size) {
    const float* x  = (const float*)d_in[0];
    const float* Wg = (const float*)d_in[1];
    const float* bg = (const float*)d_in[2];
    const float* Wv = (const float*)d_in[3];
    const float* bv = (const float*)d_in[4];
    const float* Wd = (const float*)d_in[5];
    const float* bd = (const float*)d_in[6];
    float* out = (float*)d_out;
    (void)in_sizes; (void)n_in; (void)out_size;

    split_x_kernel<<<M_TOT * D_DIM / 4 / 256, 256>>>(x);
    split_w_kernel<<<3 * D_DIM * D_DIM / 4 / 256, 256>>>(Wg, Wv, Wd);

    cudaFuncSetAttribute(gemm3_kernel,
                         cudaFuncAttributeMaxDynamicSharedMemorySize, GEMM_SMEM);
    gemm3_kernel<<<dim3(M_TOT / 128, D_DIM / 64), 256, GEMM_SMEM>>>(bg, bv, bd);

    scan_phase1<<<dim3(16, NCH), 256>>>(out);
    scan_phase2<<<16, 256>>>();
    scan_phase3<<<dim3(16, NCH - 1), 256>>>(out);
}

// round 7
// speedup vs baseline: 2.0254x; 1.5379x over previous
#include <cuda_runtime.h>
#include <cuda_fp16.h>
#include <cstdint>

// ============================================================================
// Problem dims
// ============================================================================
#define B_DIM 4
#define S_DIM 4096
#define D_DIM 1024
#define M_TOT (B_DIM * S_DIM)   // 16384
#define NCH 64
#define CHL (S_DIM / NCH)       // 64

// ============================================================================
// Device scratch (allocation-free rule -> static __device__ arrays)
// ============================================================================
__device__ __align__(128) __half g_xh[M_TOT * D_DIM];     // 32 MB (x as fp16)
__device__ __align__(128) __half g_w[3][D_DIM * D_DIM];   // 6 MB  (Wg,Wv,Wd fp16)
__device__ float g_A [M_TOT * D_DIM];                     // 64 MB (decay a)
__device__ float g_XS[M_TOT * D_DIM];                     // 64 MB (x_scan)
__device__ float g_Aprod[NCH * B_DIM * D_DIM];
__device__ float g_Hend [NCH * B_DIM * D_DIM];
__device__ float g_Hin  [NCH * B_DIM * D_DIM];

// ============================================================================
// PTX helpers (sm_80-level features: mma.sync + cp.async + ldmatrix)
// ============================================================================
__device__ __forceinline__ uint32_t smem_to_u32(const void* p) {
    uint32_t a;
    asm("{ .reg .u64 t; cvta.to.shared.u64 t, %1; cvt.u32.u64 %0, t; }"
        : "=r"(a) : "l"(p));
    return a;
}

__device__ __forceinline__ void cp16(uint32_t dst, const void* src) {
    asm volatile("cp.async.cg.shared.global [%0], [%1], 16;"
                 :: "r"(dst), "l"(src) : "memory");
}
__device__ __forceinline__ void cp_commit() {
    asm volatile("cp.async.commit_group;" ::: "memory");
}

__device__ __forceinline__ void ldsm4(uint32_t* r, uint32_t addr) {
    asm volatile("ldmatrix.sync.aligned.m8n8.x4.shared.b16 {%0,%1,%2,%3}, [%4];"
                 : "=r"(r[0]), "=r"(r[1]), "=r"(r[2]), "=r"(r[3]) : "r"(addr));
}

// D += A * B  (m16n8k16, fp16 in, f32 accum, A row-major, B col-major)
__device__ __forceinline__ void mma16816(float* c, const uint32_t* a, const uint32_t* b) {
    asm volatile(
        "mma.sync.aligned.m16n8k16.row.col.f32.f16.f16.f32 "
        "{%0,%1,%2,%3}, {%4,%5,%6,%7}, {%8,%9}, {%0,%1,%2,%3};"
        : "+f"(c[0]), "+f"(c[1]), "+f"(c[2]), "+f"(c[3])
        : "r"(a[0]), "r"(a[1]), "r"(a[2]), "r"(a[3]), "r"(b[0]), "r"(b[1]));
}

// ============================================================================
// Kernel 1: x (fp32) -> fp16
// ============================================================================
__global__ void split_x_kernel(const float* __restrict__ x) {
    int i = blockIdx.x * blockDim.x + threadIdx.x;   // float4 index
    float4 v = ((const float4*)x)[i];
    union { __half h[4]; uint2 u; } hv;
    hv.h[0] = __float2half_rn(v.x);
    hv.h[1] = __float2half_rn(v.y);
    hv.h[2] = __float2half_rn(v.z);
    hv.h[3] = __float2half_rn(v.w);
    ((uint2*)g_xh)[i] = hv.u;
}

// ============================================================================
// Kernel 2: Wg/Wv/Wd (fp32) -> fp16
// ============================================================================
__global__ void split_w_kernel(const float* __restrict__ Wg,
                               const float* __restrict__ Wv,
                               const float* __restrict__ Wd) {
    int gid = blockIdx.x * blockDim.x + threadIdx.x;   // float4 index, 3*262144
    int which = gid >> 18;
    int r = gid & ((1 << 18) - 1);
    const float* src = (which == 0) ? Wg : (which == 1) ? Wv : Wd;
    float4 v = ((const float4*)src)[r];
    union { __half h[4]; uint2 u; } hv;
    hv.h[0] = __float2half_rn(v.x);
    hv.h[1] = __float2half_rn(v.y);
    hv.h[2] = __float2half_rn(v.z);
    hv.h[3] = __float2half_rn(v.w);
    ((uint2*)g_w[which])[r] = hv.u;
}

// ============================================================================
// Kernel 3: fused triple GEMM (plain fp16) + gate epilogue + chunk aggregates
//   CTA tile: M=128, N=64, K in BK=64 chunks, double-buffered cp.async.
//   8 warps = 4(M) x 2(N); warp tile 32x32 per output, 3 outputs in regs.
//   ldmatrix fragment loads; padded 144 B smem rows (conflict-free).
//   Epilogue: gates -> g_A/g_XS, plus per-(chunk,n) scan aggregates via smem
//   (each 128-row m-tile = exactly 2 scan chunks of 64 s-steps).
// ============================================================================
#define BK 64
#define KCHUNKS 16
#define TSTRIDE_B 144                       // 64 fp16 + 8 pad, in bytes
#define XT_BYTES (128 * TSTRIDE_B)          // 18432
#define WT_BYTES (64 * TSTRIDE_B)           // 9216
#define STAGE_BYTES (XT_BYTES + 3 * WT_BYTES)       // 46080
#define GEMM_SMEM (2 * STAGE_BYTES)                 // 92160

__device__ __forceinline__ void stage_load(uint32_t sbase, int m0, int n0,
                                           int k0, int tid) {
    // x tile: 128 rows x 64 fp16 (8 x 16B per row)
    #pragma unroll
    for (int it = 0; it < 4; it++) {
        int idx = tid + it * 256;            // 0..1023
        int row = idx >> 3, c16 = idx & 7;
        cp16(sbase + row * TSTRIDE_B + c16 * 16,
             g_xh + (size_t)(m0 + row) * 1024 + k0 + c16 * 8);
    }
    // 3 W tiles: 64 rows x 64 fp16 each
    #pragma unroll
    for (int w = 0; w < 3; w++) {
        uint32_t wb = sbase + XT_BYTES + w * WT_BYTES;
        #pragma unroll
        for (int it = 0; it < 2; it++) {
            int idx = tid + it * 256;        // 0..511
            int row = idx >> 3, c16 = idx & 7;
            cp16(wb + row * TSTRIDE_B + c16 * 16,
                 g_w[w] + (size_t)(n0 + row) * 1024 + k0 + c16 * 8);
        }
    }
}

__global__ __launch_bounds__(256, 1)
void gemm3_kernel(const float* __restrict__ bgp,
                  const float* __restrict__ bvp,
                  const float* __restrict__ bdp) {
    extern __shared__ char smem[];
    const uint32_t smem_u = smem_to_u32(smem);
    const int tid  = threadIdx.x;
    const int wid  = tid >> 5;
    const int lane = tid & 31;
    const int gid  = lane >> 2;            // 0..7
    const int tig  = lane & 3;             // 0..3
    const int warp_m = wid >> 1;           // 0..3
    const int warp_n = wid & 1;            // 0..1
    const int m0 = blockIdx.x * 128;
    const int n0 = blockIdx.y * 64;

    // ldmatrix lane-address components
    const int l8   = lane & 7;             // row within 8-row matrix
    const int q    = lane >> 3;            // matrix index 0..3
    // A: matrices {m+0..7@k0, m+8..15@k0, m+0..7@k8, m+8..15@k8}
    const int a_row_off = l8 + (q & 1) * 8;
    const int a_k_off   = (q >> 1) * 16;   // bytes
    // B: matrices {nt0@k0, nt0@k8, nt1@k0, nt1@k8} (nt pair per ldsm4)
    const int b_row_off = l8 + (q >> 1) * 8;
    const int b_k_off   = (q & 1) * 16;    // bytes

    float acc[3][2][4][4];                 // [out][mt][nt][frag]
    #pragma unroll
    for (int w = 0; w < 3; w++)
        #pragma unroll
        for (int mt = 0; mt < 2; mt++)
            #pragma unroll
            for (int nt = 0; nt < 4; nt++)
                #pragma unroll
                for (int f = 0; f < 4; f++) acc[w][mt][nt][f] = 0.f;

    stage_load(smem_u, m0, n0, 0, tid);
    cp_commit();

    for (int ch = 0; ch < KCHUNKS; ch++) {
        const int buf = ch & 1;
        if (ch + 1 < KCHUNKS) {
            stage_load(smem_u + (buf ^ 1) * STAGE_BYTES, m0, n0, (ch + 1) * BK, tid);
            cp_commit();
            asm volatile("cp.async.wait_group 1;" ::: "memory");
        } else {
            asm volatile("cp.async.wait_group 0;" ::: "memory");
        }
        __syncthreads();

        const uint32_t sb = smem_u + buf * STAGE_BYTES;
        #pragma unroll
        for (int ks = 0; ks < 4; ks++) {
            // ---- A fragments via ldmatrix.x4 (2 m-tiles)
            uint32_t ah[2][4];
            #pragma unroll
            for (int mt = 0; mt < 2; mt++) {
                uint32_t addr = sb
                    + (warp_m * 32 + mt * 16 + a_row_off) * TSTRIDE_B
                    + ks * 32 + a_k_off;
                ldsm4(ah[mt], addr);
            }
            // ---- per output: B fragments (2 x ldmatrix.x4) + MMAs
            #pragma unroll
            for (int w = 0; w < 3; w++) {
                const uint32_t wb = sb + XT_BYTES + w * WT_BYTES;
                uint32_t bfr[4][2];
                #pragma unroll
                for (int p = 0; p < 2; p++) {
                    uint32_t addr = wb
                        + (warp_n * 32 + p * 16 + b_row_off) * TSTRIDE_B
                        + ks * 32 + b_k_off;
                    uint32_t r[4];
                    ldsm4(r, addr);
                    bfr[p * 2    ][0] = r[0]; bfr[p * 2    ][1] = r[1];
                    bfr[p * 2 + 1][0] = r[2]; bfr[p * 2 + 1][1] = r[3];
                }
                #pragma unroll
                for (int mt = 0; mt < 2; mt++)
                    #pragma unroll
                    for (int nt = 0; nt < 4; nt++)
                        mma16816(acc[w][mt][nt], ah[mt], bfr[nt]);
            }
        }
        __syncthreads();
    }

    // ---- epilogue: gates to global + smem park for chunk aggregates
    //   smem reuse: sA [128][65] floats, sX [128][65] floats (66560 B < 92160)
    float* sA = (float*)smem;
    float* sX = sA + 128 * 65;

    #pragma unroll
    for (int mt = 0; mt < 2; mt++) {
        #pragma unroll
        for (int half = 0; half < 2; half++) {
            const int mloc = warp_m * 32 + mt * 16 + gid + half * 8;
            const int m = m0 + mloc;
            float* Ar = g_A  + (size_t)m * 1024;
            float* Xr = g_XS + (size_t)m * 1024;
            #pragma unroll
            for (int nt = 0; nt < 4; nt++) {
                const int nl = warp_n * 32 + nt * 8 + tig * 2;
                const int n = n0 + nl;
                float2 av, xv;
                #pragma unroll
                for (int j = 0; j < 2; j++) {
                    const int f = half * 2 + j;
                    float gg = acc[0][mt][nt][f] + __ldg(bgp + n + j);
                    float vv = acc[1][mt][nt][f] + __ldg(bvp + n + j);
                    float dd = acc[2][mt][nt][f] + __ldg(bdp + n + j);
                    float sg = 1.f / (1.f + __expf(-gg));
                    float sd = 1.f / (1.f + __expf(-dd));
                    float a  = 0.001f + 0.998f * sd;
                    float xs = sg * tanhf(vv);
                    if (j == 0) { av.x = a; xv.x = xs; }
                    else        { av.y = a; xv.y = xs; }
                    sA[mloc * 65 + nl + j] = a;
                    sX[mloc * 65 + nl + j] = xs;
                }
                *(float2*)(Ar + n) = av;
                *(float2*)(Xr + n) = xv;
            }
        }
    }
    __syncthreads();

    // ---- chunk aggregates: 2 chunks x 64 columns -> 128 threads
    if (tid < 128) {
        const int chunkl = tid >> 6;      // 0..1
        const int nl = tid & 63;
        float h = 0.f, p = 1.f;
        #pragma unroll 8
        for (int i = 0; i < CHL; i++) {
            const int mloc = chunkl * CHL + i;
            float a  = sA[mloc * 65 + nl];
            float xs = sX[mloc * 65 + nl];
            h = fmaf(a, h, xs);
            p *= a;
        }
        const int b = m0 >> 12;                       // m0 / 4096
        const int chunkg = ((m0 & 4095) >> 6) + chunkl;
        const int c = b * 1024 + n0 + nl;
        g_Aprod[chunkg * 4096 + c] = p;
        g_Hend [chunkg * 4096 + c] = h;
    }
}

// ============================================================================
// Kernel 4: sequential combine of the NCH chunk aggregates per channel
// ============================================================================
__global__ void scan_phase2() {
    int c = blockIdx.x * 256 + threadIdx.x;
    float carry = 0.f;
    #pragma unroll
    for (int ch = 0; ch < NCH; ch++) {
        g_Hin[ch * 4096 + c] = carry;
        carry = fmaf(g_Aprod[ch * 4096 + c], carry, g_Hend[ch * 4096 + c]);
    }
}

// ============================================================================
// Kernel 5: apply — full local scan seeded with Hin, single pass
// ============================================================================
__global__ void scan_apply(float* __restrict__ out) {
    int c = blockIdx.x * 256 + threadIdx.x;      // channel (b*1024 + d)
    int chunk = blockIdx.y;
    float h = g_Hin[chunk * 4096 + c];
    size_t off = ((size_t)(c >> 10) * S_DIM + (size_t)chunk * CHL) * 1024 + (c & 1023);
    #pragma unroll 8
    for (int t = 0; t < CHL; t++) {
        h = fmaf(g_A[off], h, g_XS[off]);
        out[off] = h;
        off += 1024;
    }
}

// ============================================================================
// Launch
// ============================================================================
extern "C" void kernel_launch(void* const* d_in, const int* in_sizes, int n_in,
                              void* d_out, int out_size) {
    const float* x  = (const float*)d_in[0];
    const float* Wg = (const float*)d_in[1];
    const float* bg = (const float*)d_in[2];
    const float* Wv = (const float*)d_in[3];
    const float* bv = (const float*)d_in[4];
    const float* Wd = (const float*)d_in[5];
    const float* bd = (const float*)d_in[6];
    float* out = (float*)d_out;
    (void)in_sizes; (void)n_in; (void)out_size;

    split_x_kernel<<<M_TOT * D_DIM / 4 / 256, 256>>>(x);
    split_w_kernel<<<3 * D_DIM * D_DIM / 4 / 256, 256>>>(Wg, Wv, Wd);

    cudaFuncSetAttribute(gemm3_kernel,
                         cudaFuncAttributeMaxDynamicSharedMemorySize, GEMM_SMEM);
    gemm3_kernel<<<dim3(M_TOT / 128, D_DIM / 64), 256, GEMM_SMEM>>>(bg, bv, bd);

    scan_phase2<<<16, 256>>>();
    scan_apply<<<dim3(16, NCH), 256>>>(out);
}

// round 8
// speedup vs baseline: 2.4852x; 1.2270x over previous
#include <cuda_runtime.h>
#include <cuda_fp16.h>
#include <cstdint>

// ============================================================================
// Problem dims
// ============================================================================
#define B_DIM 4
#define S_DIM 4096
#define D_DIM 1024
#define M_TOT (B_DIM * S_DIM)   // 16384
#define NCH 128
#define CHL (S_DIM / NCH)       // 32

// ============================================================================
// Device scratch (allocation-free rule -> static __device__ arrays)
// ============================================================================
__device__ __align__(128) __half g_xh[M_TOT * D_DIM];     // 32 MB (x as fp16)
__device__ __align__(128) __half g_w[3][D_DIM * D_DIM];   // 6 MB  (Wg,Wv,Wd fp16)
__device__ float g_A [M_TOT * D_DIM];                     // 64 MB (decay a)
__device__ float g_XS[M_TOT * D_DIM];                     // 64 MB (x_scan)
// transposed aggregate layout: [channel][chunk], channel = b*1024 + d
__device__ __align__(128) float g_Aprod[B_DIM * D_DIM * NCH];
__device__ __align__(128) float g_Hend [B_DIM * D_DIM * NCH];
__device__ __align__(128) float g_Hin  [B_DIM * D_DIM * NCH];

// ============================================================================
// PTX helpers (sm_80-level features: mma.sync + cp.async + ldmatrix)
// ============================================================================
__device__ __forceinline__ uint32_t smem_to_u32(const void* p) {
    uint32_t a;
    asm("{ .reg .u64 t; cvta.to.shared.u64 t, %1; cvt.u32.u64 %0, t; }"
        : "=r"(a) : "l"(p));
    return a;
}

__device__ __forceinline__ void cp16(uint32_t dst, const void* src) {
    asm volatile("cp.async.cg.shared.global [%0], [%1], 16;"
                 :: "r"(dst), "l"(src) : "memory");
}
__device__ __forceinline__ void cp_commit() {
    asm volatile("cp.async.commit_group;" ::: "memory");
}

__device__ __forceinline__ void ldsm4(uint32_t* r, uint32_t addr) {
    asm volatile("ldmatrix.sync.aligned.m8n8.x4.shared.b16 {%0,%1,%2,%3}, [%4];"
                 : "=r"(r[0]), "=r"(r[1]), "=r"(r[2]), "=r"(r[3]) : "r"(addr));
}

// D += A * B  (m16n8k16, fp16 in, f32 accum, A row-major, B col-major)
__device__ __forceinline__ void mma16816(float* c, const uint32_t* a, const uint32_t* b) {
    asm volatile(
        "mma.sync.aligned.m16n8k16.row.col.f32.f16.f16.f32 "
        "{%0,%1,%2,%3}, {%4,%5,%6,%7}, {%8,%9}, {%0,%1,%2,%3};"
        : "+f"(c[0]), "+f"(c[1]), "+f"(c[2]), "+f"(c[3])
        : "r"(a[0]), "r"(a[1]), "r"(a[2]), "r"(a[3]), "r"(b[0]), "r"(b[1]));
}

// ============================================================================
// Kernel 1: x (fp32) -> fp16
// ============================================================================
__global__ void split_x_kernel(const float* __restrict__ x) {
    int i = blockIdx.x * blockDim.x + threadIdx.x;   // float4 index
    float4 v = ((const float4*)x)[i];
    union { __half h[4]; uint2 u; } hv;
    hv.h[0] = __float2half_rn(v.x);
    hv.h[1] = __float2half_rn(v.y);
    hv.h[2] = __float2half_rn(v.z);
    hv.h[3] = __float2half_rn(v.w);
    ((uint2*)g_xh)[i] = hv.u;
}

// ============================================================================
// Kernel 2: Wg/Wv/Wd (fp32) -> fp16
// ============================================================================
__global__ void split_w_kernel(const float* __restrict__ Wg,
                               const float* __restrict__ Wv,
                               const float* __restrict__ Wd) {
    int gid = blockIdx.x * blockDim.x + threadIdx.x;   // float4 index, 3*262144
    int which = gid >> 18;
    int r = gid & ((1 << 18) - 1);
    const float* src = (which == 0) ? Wg : (which == 1) ? Wv : Wd;
    float4 v = ((const float4*)src)[r];
    union { __half h[4]; uint2 u; } hv;
    hv.h[0] = __float2half_rn(v.x);
    hv.h[1] = __float2half_rn(v.y);
    hv.h[2] = __float2half_rn(v.z);
    hv.h[3] = __float2half_rn(v.w);
    ((uint2*)g_w[which])[r] = hv.u;
}

// ============================================================================
// Kernel 3: fused triple GEMM (fp16) + gate epilogue + chunk aggregates
//   CTA tile: M=256, N=64, K in BK=64 chunks, double-buffered cp.async.
//   512 threads, 16 warps = 8(M) x 2(N); warp tile 32x32 per output.
//   ldmatrix fragment loads; padded 144 B smem rows (conflict-free).
//   Epilogue: gates -> g_A/g_XS, plus per-(chunk,n) scan aggregates via smem
//   (each 256-row m-tile = exactly 8 scan chunks of 32 s-steps).
// ============================================================================
#define BK 64
#define KCHUNKS 16
#define TSTRIDE_B 144                       // 64 fp16 + 8 pad, in bytes
#define XT_BYTES (256 * TSTRIDE_B)          // 36864
#define WT_BYTES (64 * TSTRIDE_B)           // 9216
#define STAGE_BYTES (XT_BYTES + 3 * WT_BYTES)       // 64512
#define GEMM_SMEM (256 * 65 * 4 * 2)                // 133120 (epilogue park)

__device__ __forceinline__ void stage_load(uint32_t sbase, int m0, int n0,
                                           int k0, int tid) {
    // x tile: 256 rows x 64 fp16 (8 x 16B per row) = 2048 cp16 ops
    #pragma unroll
    for (int it = 0; it < 4; it++) {
        int idx = tid + it * 512;            // 0..2047
        int row = idx >> 3, c16 = idx & 7;
        cp16(sbase + row * TSTRIDE_B + c16 * 16,
             g_xh + (size_t)(m0 + row) * 1024 + k0 + c16 * 8);
    }
    // 3 W tiles: 64 rows x 64 fp16 each = 512 cp16 ops each
    #pragma unroll
    for (int w = 0; w < 3; w++) {
        int row = tid >> 3, c16 = tid & 7;
        cp16(sbase + XT_BYTES + w * WT_BYTES + row * TSTRIDE_B + c16 * 16,
             g_w[w] + (size_t)(n0 + row) * 1024 + k0 + c16 * 8);
    }
}

__global__ __launch_bounds__(512, 1)
void gemm3_kernel(const float* __restrict__ bgp,
                  const float* __restrict__ bvp,
                  const float* __restrict__ bdp) {
    extern __shared__ char smem[];
    const uint32_t smem_u = smem_to_u32(smem);
    const int tid  = threadIdx.x;
    const int wid  = tid >> 5;
    const int lane = tid & 31;
    const int gid  = lane >> 2;            // 0..7
    const int tig  = lane & 3;             // 0..3
    const int warp_m = wid >> 1;           // 0..7
    const int warp_n = wid & 1;            // 0..1
    const int m0 = blockIdx.x * 256;
    const int n0 = blockIdx.y * 64;

    // ldmatrix lane-address components
    const int l8   = lane & 7;
    const int q    = lane >> 3;
    const int a_row_off = l8 + (q & 1) * 8;
    const int a_k_off   = (q >> 1) * 16;   // bytes
    const int b_row_off = l8 + (q >> 1) * 8;
    const int b_k_off   = (q & 1) * 16;    // bytes

    float acc[3][2][4][4];                 // [out][mt][nt][frag] = 96 regs
    #pragma unroll
    for (int w = 0; w < 3; w++)
        #pragma unroll
        for (int mt = 0; mt < 2; mt++)
            #pragma unroll
            for (int nt = 0; nt < 4; nt++)
                #pragma unroll
                for (int f = 0; f < 4; f++) acc[w][mt][nt][f] = 0.f;

    stage_load(smem_u, m0, n0, 0, tid);
    cp_commit();

    for (int ch = 0; ch < KCHUNKS; ch++) {
        const int buf = ch & 1;
        if (ch + 1 < KCHUNKS) {
            stage_load(smem_u + (buf ^ 1) * STAGE_BYTES, m0, n0, (ch + 1) * BK, tid);
            cp_commit();
            asm volatile("cp.async.wait_group 1;" ::: "memory");
        } else {
            asm volatile("cp.async.wait_group 0;" ::: "memory");
        }
        __syncthreads();

        const uint32_t sb = smem_u + buf * STAGE_BYTES;
        #pragma unroll
        for (int ks = 0; ks < 4; ks++) {
            uint32_t ah[2][4];
            #pragma unroll
            for (int mt = 0; mt < 2; mt++) {
                uint32_t addr = sb
                    + (warp_m * 32 + mt * 16 + a_row_off) * TSTRIDE_B
                    + ks * 32 + a_k_off;
                ldsm4(ah[mt], addr);
            }
            #pragma unroll
            for (int w = 0; w < 3; w++) {
                const uint32_t wb = sb + XT_BYTES + w * WT_BYTES;
                uint32_t bfr[4][2];
                #pragma unroll
                for (int p = 0; p < 2; p++) {
                    uint32_t addr = wb
                        + (warp_n * 32 + p * 16 + b_row_off) * TSTRIDE_B
                        + ks * 32 + b_k_off;
                    uint32_t r[4];
                    ldsm4(r, addr);
                    bfr[p * 2    ][0] = r[0]; bfr[p * 2    ][1] = r[1];
                    bfr[p * 2 + 1][0] = r[2]; bfr[p * 2 + 1][1] = r[3];
                }
                #pragma unroll
                for (int mt = 0; mt < 2; mt++)
                    #pragma unroll
                    for (int nt = 0; nt < 4; nt++)
                        mma16816(acc[w][mt][nt], ah[mt], bfr[nt]);
            }
        }
        __syncthreads();
    }

    // ---- epilogue: gates to global + smem park for chunk aggregates
    //   smem reuse: sA [256][65] floats, sX [256][65] floats
    float* sA = (float*)smem;
    float* sX = sA + 256 * 65;

    #pragma unroll
    for (int mt = 0; mt < 2; mt++) {
        #pragma unroll
        for (int half = 0; half < 2; half++) {
            const int mloc = warp_m * 32 + mt * 16 + gid + half * 8;
            const int m = m0 + mloc;
            float* Ar = g_A  + (size_t)m * 1024;
            float* Xr = g_XS + (size_t)m * 1024;
            #pragma unroll
            for (int nt = 0; nt < 4; nt++) {
                const int nl = warp_n * 32 + nt * 8 + tig * 2;
                const int n = n0 + nl;
                float2 av, xv;
                #pragma unroll
                for (int j = 0; j < 2; j++) {
                    const int f = half * 2 + j;
                    float gg = acc[0][mt][nt][f] + __ldg(bgp + n + j);
                    float vv = acc[1][mt][nt][f] + __ldg(bvp + n + j);
                    float dd = acc[2][mt][nt][f] + __ldg(bdp + n + j);
                    float sg = 1.f / (1.f + __expf(-gg));
                    float sd = 1.f / (1.f + __expf(-dd));
                    float a  = 0.001f + 0.998f * sd;
                    float xs = sg * tanhf(vv);
                    if (j == 0) { av.x = a; xv.x = xs; }
                    else        { av.y = a; xv.y = xs; }
                    sA[mloc * 65 + nl + j] = a;
                    sX[mloc * 65 + nl + j] = xs;
                }
                *(float2*)(Ar + n) = av;
                *(float2*)(Xr + n) = xv;
            }
        }
    }
    __syncthreads();

    // ---- chunk aggregates: 8 chunks x 64 columns -> all 512 threads
    {
        const int chunkl = tid >> 6;      // 0..7
        const int nl = tid & 63;
        float h = 0.f, p = 1.f;
        #pragma unroll 8
        for (int i = 0; i < CHL; i++) {
            const int mloc = chunkl * CHL + i;
            float a  = sA[mloc * 65 + nl];
            float xs = sX[mloc * 65 + nl];
            h = fmaf(a, h, xs);
            p *= a;
        }
        const int b = m0 >> 12;                       // m0 / 4096
        const int chunkg = ((m0 & 4095) >> 5) + chunkl;
        const int c = b * 1024 + n0 + nl;
        g_Aprod[(size_t)c * NCH + chunkg] = p;
        g_Hend [(size_t)c * NCH + chunkg] = h;
    }
}

// ============================================================================
// Kernel 4: combine NCH chunk aggregates per channel (float4-batched, MLP=8)
// ============================================================================
__global__ void scan_phase2() {
    int c = blockIdx.x * 256 + threadIdx.x;      // 0..4095
    const float4* ap = (const float4*)(g_Aprod + (size_t)c * NCH);
    const float4* hp = (const float4*)(g_Hend  + (size_t)c * NCH);
    float4*       ip = (float4*)(g_Hin + (size_t)c * NCH);
    float carry = 0.f;
    #pragma unroll
    for (int b8 = 0; b8 < NCH / 8; b8++) {
        float4 a0 = ap[b8 * 2], a1 = ap[b8 * 2 + 1];
        float4 h0 = hp[b8 * 2], h1 = hp[b8 * 2 + 1];
        float4 i0, i1;
        i0.x = carry; carry = fmaf(a0.x, carry, h0.x);
        i0.y = carry; carry = fmaf(a0.y, carry, h0.y);
        i0.z = carry; carry = fmaf(a0.z, carry, h0.z);
        i0.w = carry; carry = fmaf(a0.w, carry, h0.w);
        i1.x = carry; carry = fmaf(a1.x, carry, h1.x);
        i1.y = carry; carry = fmaf(a1.y, carry, h1.y);
        i1.z = carry; carry = fmaf(a1.z, carry, h1.z);
        i1.w = carry; carry = fmaf(a1.w, carry, h1.w);
        ip[b8 * 2] = i0; ip[b8 * 2 + 1] = i1;
    }
}

// ============================================================================
// Kernel 5: apply — full local scan seeded with Hin (float2 per thread)
// ============================================================================
__global__ void scan_apply(float* __restrict__ out) {
    int c = 2 * (blockIdx.x * 256 + threadIdx.x);  // channel pair (b*1024 + d)
    int chunk = blockIdx.y;
    float h0 = g_Hin[(size_t)c       * NCH + chunk];
    float h1 = g_Hin[(size_t)(c + 1) * NCH + chunk];
    size_t off = ((size_t)(c >> 10) * S_DIM + (size_t)chunk * CHL) * 1024 + (c & 1023);
    #pragma unroll 8
    for (int t = 0; t < CHL; t++) {
        float2 a  = *(const float2*)(g_A  + off);
        float2 xs = *(const float2*)(g_XS + off);
        h0 = fmaf(a.x, h0, xs.x);
        h1 = fmaf(a.y, h1, xs.y);
        *(float2*)(out + off) = make_float2(h0, h1);
        off += 1024;
    }
}

// ============================================================================
// Launch
// ============================================================================
extern "C" void kernel_launch(void* const* d_in, const int* in_sizes, int n_in,
                              void* d_out, int out_size) {
    const float* x  = (const float*)d_in[0];
    const float* Wg = (const float*)d_in[1];
    const float* bg = (const float*)d_in[2];
    const float* Wv = (const float*)d_in[3];
    const float* bv = (const float*)d_in[4];
    const float* Wd = (const float*)d_in[5];
    const float* bd = (const float*)d_in[6];
    float* out = (float*)d_out;
    (void)in_sizes; (void)n_in; (void)out_size;

    split_x_kernel<<<M_TOT * D_DIM / 4 / 256, 256>>>(x);
    split_w_kernel<<<3 * D_DIM * D_DIM / 4 / 256, 256>>>(Wg, Wv, Wd);

    cudaFuncSetAttribute(gemm3_kernel,
                         cudaFuncAttributeMaxDynamicSharedMemorySize, GEMM_SMEM);
    gemm3_kernel<<<dim3(M_TOT / 256, D_DIM / 64), 512, GEMM_SMEM>>>(bg, bv, bd);

    scan_phase2<<<16, 256>>>();
    scan_apply<<<dim3(8, NCH), 256>>>(out);
}

// round 9
// speedup vs baseline: 2.5150x; 1.0120x over previous
#include <cuda_runtime.h>
#include <cuda_fp16.h>
#include <cstdint>

// ============================================================================
// Problem dims
// ============================================================================
#define B_DIM 4
#define S_DIM 4096
#define D_DIM 1024
#define M_TOT (B_DIM * S_DIM)   // 16384
#define NCH 128
#define CHL (S_DIM / NCH)       // 32

// ============================================================================
// Device scratch (allocation-free rule -> static __device__ arrays)
// ============================================================================
__device__ __align__(128) __half g_xh[M_TOT * D_DIM];     // 32 MB (x as fp16)
__device__ __align__(128) __half g_w[3][D_DIM * D_DIM];   // 6 MB  (Wg,Wv,Wd fp16)
__device__ float g_A [M_TOT * D_DIM];                     // 64 MB (decay a)
__device__ float g_XS[M_TOT * D_DIM];                     // 64 MB (x_scan)
// transposed aggregate layout: [channel][chunk], channel = b*1024 + d
__device__ __align__(128) float g_Aprod[B_DIM * D_DIM * NCH];
__device__ __align__(128) float g_Hend [B_DIM * D_DIM * NCH];
__device__ __align__(128) float g_Hin  [B_DIM * D_DIM * NCH];

// ============================================================================
// PTX helpers (sm_80-level features: mma.sync + cp.async + ldmatrix)
// ============================================================================
__device__ __forceinline__ uint32_t smem_to_u32(const void* p) {
    uint32_t a;
    asm("{ .reg .u64 t; cvta.to.shared.u64 t, %1; cvt.u32.u64 %0, t; }"
        : "=r"(a) : "l"(p));
    return a;
}

__device__ __forceinline__ void cp16(uint32_t dst, const void* src) {
    asm volatile("cp.async.cg.shared.global [%0], [%1], 16;"
                 :: "r"(dst), "l"(src) : "memory");
}
__device__ __forceinline__ void cp_commit() {
    asm volatile("cp.async.commit_group;" ::: "memory");
}

__device__ __forceinline__ void ldsm4(uint32_t* r, uint32_t addr) {
    asm volatile("ldmatrix.sync.aligned.m8n8.x4.shared.b16 {%0,%1,%2,%3}, [%4];"
                 : "=r"(r[0]), "=r"(r[1]), "=r"(r[2]), "=r"(r[3]) : "r"(addr));
}

// D += A * B  (m16n8k16, fp16 in, f32 accum, A row-major, B col-major)
__device__ __forceinline__ void mma16816(float* c, const uint32_t* a, const uint32_t* b) {
    asm volatile(
        "mma.sync.aligned.m16n8k16.row.col.f32.f16.f16.f32 "
        "{%0,%1,%2,%3}, {%4,%5,%6,%7}, {%8,%9}, {%0,%1,%2,%3};"
        : "+f"(c[0]), "+f"(c[1]), "+f"(c[2]), "+f"(c[3])
        : "r"(a[0]), "r"(a[1]), "r"(a[2]), "r"(a[3]), "r"(b[0]), "r"(b[1]));
}

// ============================================================================
// Kernel 1: fused fp32 -> fp16 conversion for x and Wg/Wv/Wd
// ============================================================================
#define X_F4   (M_TOT * D_DIM / 4)          // 4194304 float4s
#define W_F4   (D_DIM * D_DIM / 4)          // 262144 per matrix
#define CVT_F4 (X_F4 + 3 * W_F4)            // 4980736

__global__ void convert_kernel(const float* __restrict__ x,
                               const float* __restrict__ Wg,
                               const float* __restrict__ Wv,
                               const float* __restrict__ Wd) {
    int gid = blockIdx.x * blockDim.x + threadIdx.x;
    const float* src;
    uint2* dst;
    int r;
    if (gid < X_F4) {
        src = x; dst = (uint2*)g_xh; r = gid;
    } else {
        int t = gid - X_F4;
        int which = t / W_F4;
        r = t - which * W_F4;
        src = (which == 0) ? Wg : (which == 1) ? Wv : Wd;
        dst = (uint2*)g_w[which];
    }
    float4 v = ((const float4*)src)[r];
    union { __half h[4]; uint2 u; } hv;
    hv.h[0] = __float2half_rn(v.x);
    hv.h[1] = __float2half_rn(v.y);
    hv.h[2] = __float2half_rn(v.z);
    hv.h[3] = __float2half_rn(v.w);
    dst[r] = hv.u;
}

// ============================================================================
// Kernel 2: fused triple GEMM (fp16) + gate epilogue + chunk aggregates
//   CTA tile: M=256, N=64, K in BK=64 chunks, 3-stage cp.async pipeline
//   (prefetch distance 2, ONE __syncthreads per chunk).
//   512 threads, 16 warps = 8(M) x 2(N); warp tile 32x32 per output.
//   ldmatrix fragment loads; padded 144 B smem rows (conflict-free).
//   Epilogue: gates -> g_A/g_XS, plus per-(chunk,n) scan aggregates via smem.
// ============================================================================
#define BK 64
#define KCHUNKS 16
#define NSTAGE 3
#define TSTRIDE_B 144                       // 64 fp16 + 8 pad, in bytes
#define XT_BYTES (256 * TSTRIDE_B)          // 36864
#define WT_BYTES (64 * TSTRIDE_B)           // 9216
#define STAGE_BYTES (XT_BYTES + 3 * WT_BYTES)       // 64512
#define GEMM_SMEM (NSTAGE * STAGE_BYTES)            // 193536

__device__ __forceinline__ void stage_load(uint32_t sbase, int m0, int n0,
                                           int k0, int tid) {
    // x tile: 256 rows x 64 fp16 (8 x 16B per row) = 2048 cp16 ops
    #pragma unroll
    for (int it = 0; it < 4; it++) {
        int idx = tid + it * 512;            // 0..2047
        int row = idx >> 3, c16 = idx & 7;
        cp16(sbase + row * TSTRIDE_B + c16 * 16,
             g_xh + (size_t)(m0 + row) * 1024 + k0 + c16 * 8);
    }
    // 3 W tiles: 64 rows x 64 fp16 each = 512 cp16 ops each
    #pragma unroll
    for (int w = 0; w < 3; w++) {
        int row = tid >> 3, c16 = tid & 7;
        cp16(sbase + XT_BYTES + w * WT_BYTES + row * TSTRIDE_B + c16 * 16,
             g_w[w] + (size_t)(n0 + row) * 1024 + k0 + c16 * 8);
    }
}

__global__ __launch_bounds__(512, 1)
void gemm3_kernel(const float* __restrict__ bgp,
                  const float* __restrict__ bvp,
                  const float* __restrict__ bdp) {
    extern __shared__ char smem[];
    const uint32_t smem_u = smem_to_u32(smem);
    const int tid  = threadIdx.x;
    const int wid  = tid >> 5;
    const int lane = tid & 31;
    const int gid  = lane >> 2;            // 0..7
    const int tig  = lane & 3;             // 0..3
    const int warp_m = wid >> 1;           // 0..7
    const int warp_n = wid & 1;            // 0..1
    const int m0 = blockIdx.x * 256;
    const int n0 = blockIdx.y * 64;

    // ldmatrix lane-address components
    const int l8   = lane & 7;
    const int q    = lane >> 3;
    const int a_row_off = l8 + (q & 1) * 8;
    const int a_k_off   = (q >> 1) * 16;   // bytes
    const int b_row_off = l8 + (q >> 1) * 8;
    const int b_k_off   = (q & 1) * 16;    // bytes

    float acc[3][2][4][4];                 // [out][mt][nt][frag] = 96 regs
    #pragma unroll
    for (int w = 0; w < 3; w++)
        #pragma unroll
        for (int mt = 0; mt < 2; mt++)
            #pragma unroll
            for (int nt = 0; nt < 4; nt++)
                #pragma unroll
                for (int f = 0; f < 4; f++) acc[w][mt][nt][f] = 0.f;

    // prologue: fill stages 0 and 1
    stage_load(smem_u,               m0, n0, 0,  tid); cp_commit();
    stage_load(smem_u + STAGE_BYTES, m0, n0, BK, tid); cp_commit();

    int sidx = 0;   // buffer index of current stage (stage ch -> ch % 3)
    for (int ch = 0; ch < KCHUNKS; ch++) {
        // stage ch must be complete; at most stage ch+1 may remain in flight
        if (ch + 1 < KCHUNKS)
            asm volatile("cp.async.wait_group 1;" ::: "memory");
        else
            asm volatile("cp.async.wait_group 0;" ::: "memory");
        __syncthreads();   // also orders prior-iteration reads before new stores

        // prefetch stage ch+2 into buffer (ch+2)%3 (= buffer of stage ch-1)
        if (ch + 2 < KCHUNKS) {
            int pidx = sidx + 2 >= NSTAGE ? sidx + 2 - NSTAGE : sidx + 2;
            stage_load(smem_u + pidx * STAGE_BYTES, m0, n0, (ch + 2) * BK, tid);
            cp_commit();
        }

        const uint32_t sb = smem_u + sidx * STAGE_BYTES;
        #pragma unroll
        for (int ks = 0; ks < 4; ks++) {
            uint32_t ah[2][4];
            #pragma unroll
            for (int mt = 0; mt < 2; mt++) {
                uint32_t addr = sb
                    + (warp_m * 32 + mt * 16 + a_row_off) * TSTRIDE_B
                    + ks * 32 + a_k_off;
                ldsm4(ah[mt], addr);
            }
            #pragma unroll
            for (int w = 0; w < 3; w++) {
                const uint32_t wb = sb + XT_BYTES + w * WT_BYTES;
                uint32_t bfr[4][2];
                #pragma unroll
                for (int p = 0; p < 2; p++) {
                    uint32_t addr = wb
                        + (warp_n * 32 + p * 16 + b_row_off) * TSTRIDE_B
                        + ks * 32 + b_k_off;
                    uint32_t r[4];
                    ldsm4(r, addr);
                    bfr[p * 2    ][0] = r[0]; bfr[p * 2    ][1] = r[1];
                    bfr[p * 2 + 1][0] = r[2]; bfr[p * 2 + 1][1] = r[3];
                }
                #pragma unroll
                for (int mt = 0; mt < 2; mt++)
                    #pragma unroll
                    for (int nt = 0; nt < 4; nt++)
                        mma16816(acc[w][mt][nt], ah[mt], bfr[nt]);
            }
        }
        sidx = sidx + 1 >= NSTAGE ? 0 : sidx + 1;
    }
    __syncthreads();   // all warps done with stage buffers before smem reuse

    // ---- epilogue: gates to global + smem park for chunk aggregates
    //   smem reuse: sA [256][65] floats, sX [256][65] floats (133120 B)
    float* sA = (float*)smem;
    float* sX = sA + 256 * 65;

    #pragma unroll
    for (int mt = 0; mt < 2; mt++) {
        #pragma unroll
        for (int half = 0; half < 2; half++) {
            const int mloc = warp_m * 32 + mt * 16 + gid + half * 8;
            const int m = m0 + mloc;
            float* Ar = g_A  + (size_t)m * 1024;
            float* Xr = g_XS + (size_t)m * 1024;
            #pragma unroll
            for (int nt = 0; nt < 4; nt++) {
                const int nl = warp_n * 32 + nt * 8 + tig * 2;
                const int n = n0 + nl;
                float2 av, xv;
                #pragma unroll
                for (int j = 0; j < 2; j++) {
                    const int f = half * 2 + j;
                    float gg = acc[0][mt][nt][f] + __ldg(bgp + n + j);
                    float vv = acc[1][mt][nt][f] + __ldg(bvp + n + j);
                    float dd = acc[2][mt][nt][f] + __ldg(bdp + n + j);
                    float sg = 1.f / (1.f + __expf(-gg));
                    float sd = 1.f / (1.f + __expf(-dd));
                    float a  = 0.001f + 0.998f * sd;
                    float xs = sg * tanhf(vv);
                    if (j == 0) { av.x = a; xv.x = xs; }
                    else        { av.y = a; xv.y = xs; }
                    sA[mloc * 65 + nl + j] = a;
                    sX[mloc * 65 + nl + j] = xs;
                }
                *(float2*)(Ar + n) = av;
                *(float2*)(Xr + n) = xv;
            }
        }
    }
    __syncthreads();

    // ---- chunk aggregates: 8 chunks x 64 columns -> all 512 threads
    {
        const int chunkl = tid >> 6;      // 0..7
        const int nl = tid & 63;
        float h = 0.f, p = 1.f;
        #pragma unroll 8
        for (int i = 0; i < CHL; i++) {
            const int mloc = chunkl * CHL + i;
            float a  = sA[mloc * 65 + nl];
            float xs = sX[mloc * 65 + nl];
            h = fmaf(a, h, xs);
            p *= a;
        }
        const int b = m0 >> 12;                       // m0 / 4096
        const int chunkg = ((m0 & 4095) >> 5) + chunkl;
        const int c = b * 1024 + n0 + nl;
        g_Aprod[(size_t)c * NCH + chunkg] = p;
        g_Hend [(size_t)c * NCH + chunkg] = h;
    }
}

// ============================================================================
// Kernel 3: combine NCH chunk aggregates per channel.
//   One warp per channel: 4 elements/lane + warp shuffle scan over the
//   associative op  (A,X) o (A',X') = (A*A', A'*X + X').
// ============================================================================
__global__ void scan_phase2() {
    const int lane = threadIdx.x & 31;
    const int c = blockIdx.x * 8 + (threadIdx.x >> 5);   // channel 0..4095
    const float4* ap = (const float4*)(g_Aprod + (size_t)c * NCH) + lane;
    const float4* hp = (const float4*)(g_Hend  + (size_t)c * NCH) + lane;
    float4 a = *ap;
    float4 h = *hp;

    // lane-local totals over 4 chunks
    float TX = h.x;
    TX = fmaf(a.y, TX, h.y);
    TX = fmaf(a.z, TX, h.z);
    TX = fmaf(a.w, TX, h.w);
    float TA = a.x * a.y * a.z * a.w;

    // warp inclusive scan: cur = op(prev, cur)
    #pragma unroll
    for (int d = 1; d < 32; d <<= 1) {
        float pA = __shfl_up_sync(0xFFFFFFFFu, TA, d);
        float pX = __shfl_up_sync(0xFFFFFFFFu, TX, d);
        if (lane >= d) {
            TX = fmaf(TA, pX, TX);
            TA = TA * pA;
        }
    }
    // exclusive
    float eX = __shfl_up_sync(0xFFFFFFFFu, TX, 1);
    if (lane == 0) eX = 0.f;

    // per-chunk carries: Hin_{j+1} = a_j * Hin_j + h_j
    float4 o;
    o.x = eX;
    o.y = fmaf(a.x, o.x, h.x);
    o.z = fmaf(a.y, o.y, h.y);
    o.w = fmaf(a.z, o.z, h.z);
    ((float4*)(g_Hin + (size_t)c * NCH))[lane] = o;
}

// ============================================================================
// Kernel 4: apply — full local scan seeded with Hin (float2 per thread)
// ============================================================================
__global__ void scan_apply(float* __restrict__ out) {
    int c = 2 * (blockIdx.x * 256 + threadIdx.x);  // channel pair (b*1024 + d)
    int chunk = blockIdx.y;
    float h0 = g_Hin[(size_t)c       * NCH + chunk];
    float h1 = g_Hin[(size_t)(c + 1) * NCH + chunk];
    size_t off = ((size_t)(c >> 10) * S_DIM + (size_t)chunk * CHL) * 1024 + (c & 1023);
    #pragma unroll 8
    for (int t = 0; t < CHL; t++) {
        float2 a  = *(const float2*)(g_A  + off);
        float2 xs = *(const float2*)(g_XS + off);
        h0 = fmaf(a.x, h0, xs.x);
        h1 = fmaf(a.y, h1, xs.y);
        *(float2*)(out + off) = make_float2(h0, h1);
        off += 1024;
    }
}

// ============================================================================
// Launch
// ============================================================================
extern "C" void kernel_launch(void* const* d_in, const int* in_sizes, int n_in,
                              void* d_out, int out_size) {
    const float* x  = (const float*)d_in[0];
    const float* Wg = (const float*)d_in[1];
    const float* bg = (const float*)d_in[2];
    const float* Wv = (const float*)d_in[3];
    const float* bv = (const float*)d_in[4];
    const float* Wd = (const float*)d_in[5];
    const float* bd = (const float*)d_in[6];
    float* out = (float*)d_out;
    (void)in_sizes; (void)n_in; (void)out_size;

    convert_kernel<<<CVT_F4 / 256, 256>>>(x, Wg, Wv, Wd);

    cudaFuncSetAttribute(gemm3_kernel,
                         cudaFuncAttributeMaxDynamicSharedMemorySize, GEMM_SMEM);
    gemm3_kernel<<<dim3(M_TOT / 256, D_DIM / 64), 512, GEMM_SMEM>>>(bg, bv, bd);

    scan_phase2<<<512, 256>>>();
    scan_apply<<<dim3(8, NCH), 256>>>(out);
}

// round 10
// speedup vs baseline: 2.7146x; 1.0794x over previous
#include <cuda_runtime.h>
#include <cuda_fp16.h>
#include <cstdint>

// ============================================================================
// Problem dims
// ============================================================================
#define B_DIM 4
#define S_DIM 4096
#define D_DIM 1024
#define M_TOT (B_DIM * S_DIM)   // 16384
#define NCH 128
#define CHL (S_DIM / NCH)       // 32

// ============================================================================
// Device scratch (allocation-free rule -> static __device__ arrays)
// ============================================================================
__device__ __align__(128) __half g_xh[M_TOT * D_DIM];     // 32 MB (x as fp16)
__device__ __align__(128) __half g_w[3][D_DIM * D_DIM];   // 6 MB  (Wg,Wv,Wd fp16)
// interleaved (a, xs) pairs, one __half2 per (m, d)
__device__ __align__(128) __half2 g_AX[M_TOT * D_DIM];    // 64 MB
// transposed aggregate layout: [channel][chunk], channel = b*1024 + d
__device__ __align__(128) float g_Aprod[B_DIM * D_DIM * NCH];
__device__ __align__(128) float g_Hend [B_DIM * D_DIM * NCH];
__device__ __align__(128) float g_Hin  [B_DIM * D_DIM * NCH];

// ============================================================================
// PTX helpers (sm_80-level features: mma.sync + cp.async + ldmatrix)
// ============================================================================
__device__ __forceinline__ uint32_t smem_to_u32(const void* p) {
    uint32_t a;
    asm("{ .reg .u64 t; cvta.to.shared.u64 t, %1; cvt.u32.u64 %0, t; }"
        : "=r"(a) : "l"(p));
    return a;
}

__device__ __forceinline__ void cp16(uint32_t dst, const void* src) {
    asm volatile("cp.async.cg.shared.global [%0], [%1], 16;"
                 :: "r"(dst), "l"(src) : "memory");
}
__device__ __forceinline__ void cp_commit() {
    asm volatile("cp.async.commit_group;" ::: "memory");
}

__device__ __forceinline__ void ldsm4(uint32_t* r, uint32_t addr) {
    asm volatile("ldmatrix.sync.aligned.m8n8.x4.shared.b16 {%0,%1,%2,%3}, [%4];"
                 : "=r"(r[0]), "=r"(r[1]), "=r"(r[2]), "=r"(r[3]) : "r"(addr));
}

// D += A * B  (m16n8k16, fp16 in, f32 accum, A row-major, B col-major)
__device__ __forceinline__ void mma16816(float* c, const uint32_t* a, const uint32_t* b) {
    asm volatile(
        "mma.sync.aligned.m16n8k16.row.col.f32.f16.f16.f32 "
        "{%0,%1,%2,%3}, {%4,%5,%6,%7}, {%8,%9}, {%0,%1,%2,%3};"
        : "+f"(c[0]), "+f"(c[1]), "+f"(c[2]), "+f"(c[3])
        : "r"(a[0]), "r"(a[1]), "r"(a[2]), "r"(a[3]), "r"(b[0]), "r"(b[1]));
}

// ============================================================================
// Kernel 1: fused fp32 -> fp16 conversion for x and Wg/Wv/Wd
// ============================================================================
#define X_F4   (M_TOT * D_DIM / 4)          // 4194304 float4s
#define W_F4   (D_DIM * D_DIM / 4)          // 262144 per matrix
#define CVT_F4 (X_F4 + 3 * W_F4)            // 4980736

__global__ void convert_kernel(const float* __restrict__ x,
                               const float* __restrict__ Wg,
                               const float* __restrict__ Wv,
                               const float* __restrict__ Wd) {
    int gid = blockIdx.x * blockDim.x + threadIdx.x;
    const float* src;
    uint2* dst;
    int r;
    if (gid < X_F4) {
        src = x; dst = (uint2*)g_xh; r = gid;
    } else {
        int t = gid - X_F4;
        int which = t / W_F4;
        r = t - which * W_F4;
        src = (which == 0) ? Wg : (which == 1) ? Wv : Wd;
        dst = (uint2*)g_w[which];
    }
    float4 v = ((const float4*)src)[r];
    union { __half h[4]; uint2 u; } hv;
    hv.h[0] = __float2half_rn(v.x);
    hv.h[1] = __float2half_rn(v.y);
    hv.h[2] = __float2half_rn(v.z);
    hv.h[3] = __float2half_rn(v.w);
    dst[r] = hv.u;
}

// ============================================================================
// Kernel 2: fused triple GEMM (fp16) + gate epilogue + chunk aggregates
//   CTA tile: M=256, N=64, K in BK=64 chunks, 3-stage cp.async pipeline
//   (prefetch distance 2, ONE __syncthreads per chunk).
//   512 threads, 16 warps = 8(M) x 2(N); warp tile 32x32 per output.
//   Epilogue: half2 (a,xs) -> g_AX; chunk aggregates computed from the
//   QUANTIZED values so the parallel scan is internally consistent.
// ============================================================================
#define BK 64
#define KCHUNKS 16
#define NSTAGE 3
#define TSTRIDE_B 144                       // 64 fp16 + 8 pad, in bytes
#define XT_BYTES (256 * TSTRIDE_B)          // 36864
#define WT_BYTES (64 * TSTRIDE_B)           // 9216
#define STAGE_BYTES (XT_BYTES + 3 * WT_BYTES)       // 64512
#define GEMM_SMEM (NSTAGE * STAGE_BYTES)            // 193536

__device__ __forceinline__ void stage_load(uint32_t sbase, int m0, int n0,
                                           int k0, int tid) {
    // x tile: 256 rows x 64 fp16 (8 x 16B per row) = 2048 cp16 ops
    #pragma unroll
    for (int it = 0; it < 4; it++) {
        int idx = tid + it * 512;            // 0..2047
        int row = idx >> 3, c16 = idx & 7;
        cp16(sbase + row * TSTRIDE_B + c16 * 16,
             g_xh + (size_t)(m0 + row) * 1024 + k0 + c16 * 8);
    }
    // 3 W tiles: 64 rows x 64 fp16 each = 512 cp16 ops each
    #pragma unroll
    for (int w = 0; w < 3; w++) {
        int row = tid >> 3, c16 = tid & 7;
        cp16(sbase + XT_BYTES + w * WT_BYTES + row * TSTRIDE_B + c16 * 16,
             g_w[w] + (size_t)(n0 + row) * 1024 + k0 + c16 * 8);
    }
}

__global__ __launch_bounds__(512, 1)
void gemm3_kernel(const float* __restrict__ bgp,
                  const float* __restrict__ bvp,
                  const float* __restrict__ bdp) {
    extern __shared__ char smem[];
    const uint32_t smem_u = smem_to_u32(smem);
    const int tid  = threadIdx.x;
    const int wid  = tid >> 5;
    const int lane = tid & 31;
    const int gid  = lane >> 2;            // 0..7
    const int tig  = lane & 3;             // 0..3
    const int warp_m = wid >> 1;           // 0..7
    const int warp_n = wid & 1;            // 0..1
    const int m0 = blockIdx.x * 256;
    const int n0 = blockIdx.y * 64;

    // ldmatrix lane-address components
    const int l8   = lane & 7;
    const int q    = lane >> 3;
    const int a_row_off = l8 + (q & 1) * 8;
    const int a_k_off   = (q >> 1) * 16;   // bytes
    const int b_row_off = l8 + (q >> 1) * 8;
    const int b_k_off   = (q & 1) * 16;    // bytes

    float acc[3][2][4][4];                 // [out][mt][nt][frag] = 96 regs
    #pragma unroll
    for (int w = 0; w < 3; w++)
        #pragma unroll
        for (int mt = 0; mt < 2; mt++)
            #pragma unroll
            for (int nt = 0; nt < 4; nt++)
                #pragma unroll
                for (int f = 0; f < 4; f++) acc[w][mt][nt][f] = 0.f;

    // prologue: fill stages 0 and 1
    stage_load(smem_u,               m0, n0, 0,  tid); cp_commit();
    stage_load(smem_u + STAGE_BYTES, m0, n0, BK, tid); cp_commit();

    int sidx = 0;   // buffer index of current stage (stage ch -> ch % 3)
    for (int ch = 0; ch < KCHUNKS; ch++) {
        if (ch + 1 < KCHUNKS)
            asm volatile("cp.async.wait_group 1;" ::: "memory");
        else
            asm volatile("cp.async.wait_group 0;" ::: "memory");
        __syncthreads();   // orders prior-iteration reads before new stores

        if (ch + 2 < KCHUNKS) {
            int pidx = sidx + 2 >= NSTAGE ? sidx + 2 - NSTAGE : sidx + 2;
            stage_load(smem_u + pidx * STAGE_BYTES, m0, n0, (ch + 2) * BK, tid);
            cp_commit();
        }

        const uint32_t sb = smem_u + sidx * STAGE_BYTES;
        #pragma unroll
        for (int ks = 0; ks < 4; ks++) {
            uint32_t ah[2][4];
            #pragma unroll
            for (int mt = 0; mt < 2; mt++) {
                uint32_t addr = sb
                    + (warp_m * 32 + mt * 16 + a_row_off) * TSTRIDE_B
                    + ks * 32 + a_k_off;
                ldsm4(ah[mt], addr);
            }
            #pragma unroll
            for (int w = 0; w < 3; w++) {
                const uint32_t wb = sb + XT_BYTES + w * WT_BYTES;
                uint32_t bfr[4][2];
                #pragma unroll
                for (int p = 0; p < 2; p++) {
                    uint32_t addr = wb
                        + (warp_n * 32 + p * 16 + b_row_off) * TSTRIDE_B
                        + ks * 32 + b_k_off;
                    uint32_t r[4];
                    ldsm4(r, addr);
                    bfr[p * 2    ][0] = r[0]; bfr[p * 2    ][1] = r[1];
                    bfr[p * 2 + 1][0] = r[2]; bfr[p * 2 + 1][1] = r[3];
                }
                #pragma unroll
                for (int mt = 0; mt < 2; mt++)
                    #pragma unroll
                    for (int nt = 0; nt < 4; nt++)
                        mma16816(acc[w][mt][nt], ah[mt], bfr[nt]);
            }
        }
        sidx = sidx + 1 >= NSTAGE ? 0 : sidx + 1;
    }
    __syncthreads();   // all warps done with stage buffers before smem reuse

    // ---- epilogue: quantized half2 (a,xs) to global + smem park (quantized)
    //   smem reuse: sA [256][65] floats, sX [256][65] floats (133120 B)
    float* sA = (float*)smem;
    float* sX = sA + 256 * 65;

    #pragma unroll
    for (int mt = 0; mt < 2; mt++) {
        #pragma unroll
        for (int half = 0; half < 2; half++) {
            const int mloc = warp_m * 32 + mt * 16 + gid + half * 8;
            const int m = m0 + mloc;
            __half2* AXr = g_AX + (size_t)m * 1024;
            #pragma unroll
            for (int nt = 0; nt < 4; nt++) {
                const int nl = warp_n * 32 + nt * 8 + tig * 2;
                const int n = n0 + nl;
                uint2 pk;
                #pragma unroll
                for (int j = 0; j < 2; j++) {
                    const int f = half * 2 + j;
                    float gg = acc[0][mt][nt][f] + __ldg(bgp + n + j);
                    float vv = acc[1][mt][nt][f] + __ldg(bvp + n + j);
                    float dd = acc[2][mt][nt][f] + __ldg(bdp + n + j);
                    float sg = 1.f / (1.f + __expf(-gg));
                    float sd = 1.f / (1.f + __expf(-dd));
                    float a  = 0.001f + 0.998f * sd;
                    float xs = sg * tanhf(vv);
                    __half2 qh = __floats2half2_rn(a, xs);
                    float2 qf = __half22float2(qh);      // quantized values
                    sA[mloc * 65 + nl + j] = qf.x;
                    sX[mloc * 65 + nl + j] = qf.y;
                    ((uint32_t*)&pk)[j] = *(uint32_t*)&qh;
                }
                *(uint2*)(AXr + n) = pk;                 // 8B store, 2 half2
            }
        }
    }
    __syncthreads();

    // ---- chunk aggregates (from quantized values): 8 chunks x 64 columns
    {
        const int chunkl = tid >> 6;      // 0..7
        const int nl = tid & 63;
        float h = 0.f, p = 1.f;
        #pragma unroll 8
        for (int i = 0; i < CHL; i++) {
            const int mloc = chunkl * CHL + i;
            float a  = sA[mloc * 65 + nl];
            float xs = sX[mloc * 65 + nl];
            h = fmaf(a, h, xs);
            p *= a;
        }
        const int b = m0 >> 12;                       // m0 / 4096
        const int chunkg = ((m0 & 4095) >> 5) + chunkl;
        const int c = b * 1024 + n0 + nl;
        g_Aprod[(size_t)c * NCH + chunkg] = p;
        g_Hend [(size_t)c * NCH + chunkg] = h;
    }
}

// ============================================================================
// Kernel 3: combine NCH chunk aggregates per channel.
//   One warp per channel: 4 elements/lane + warp shuffle scan over the
//   associative op  (A,X) o (A',X') = (A*A', A'*X + X').
// ============================================================================
__global__ void scan_phase2() {
    const int lane = threadIdx.x & 31;
    const int c = blockIdx.x * 8 + (threadIdx.x >> 5);   // channel 0..4095
    float4 a = ((const float4*)(g_Aprod + (size_t)c * NCH))[lane];
    float4 h = ((const float4*)(g_Hend  + (size_t)c * NCH))[lane];

    // lane-local totals over 4 chunks
    float TX = h.x;
    TX = fmaf(a.y, TX, h.y);
    TX = fmaf(a.z, TX, h.z);
    TX = fmaf(a.w, TX, h.w);
    float TA = a.x * a.y * a.z * a.w;

    // warp inclusive scan: cur = op(prev, cur)
    #pragma unroll
    for (int d = 1; d < 32; d <<= 1) {
        float pA = __shfl_up_sync(0xFFFFFFFFu, TA, d);
        float pX = __shfl_up_sync(0xFFFFFFFFu, TX, d);
        if (lane >= d) {
            TX = fmaf(TA, pX, TX);
            TA = TA * pA;
        }
    }
    // exclusive
    float eX = __shfl_up_sync(0xFFFFFFFFu, TX, 1);
    if (lane == 0) eX = 0.f;

    // per-chunk carries: Hin_{j+1} = a_j * Hin_j + h_j
    float4 o;
    o.x = eX;
    o.y = fmaf(a.x, o.x, h.x);
    o.z = fmaf(a.y, o.y, h.y);
    o.w = fmaf(a.z, o.z, h.z);
    ((float4*)(g_Hin + (size_t)c * NCH))[lane] = o;
}

// ============================================================================
// Kernel 4: apply — local scan seeded with Hin, 4 channels per thread
//   (one uint4 = 4 half2 (a,xs) pairs in, one float4 out, per time step)
// ============================================================================
__global__ void scan_apply(float* __restrict__ out) {
    const int c4 = blockIdx.x * 256 + threadIdx.x;   // 0..1023 (channel quad)
    const int b = c4 >> 8;
    const int dbase = (c4 & 255) * 4;
    const int chunk = blockIdx.y;

    float h[4];
    #pragma unroll
    for (int j = 0; j < 4; j++)
        h[j] = g_Hin[(size_t)(b * 1024 + dbase + j) * NCH + chunk];

    size_t off = ((size_t)b * S_DIM + (size_t)chunk * CHL) * 1024 + dbase;
    #pragma unroll 8
    for (int t = 0; t < CHL; t++) {
        uint4 raw = *(const uint4*)(g_AX + off);
        float4 o;
        #pragma unroll
        for (int j = 0; j < 4; j++) {
            __half2 ax = *(__half2*)(((uint32_t*)&raw) + j);
            float2 axf = __half22float2(ax);
            h[j] = fmaf(axf.x, h[j], axf.y);
            ((float*)&o)[j] = h[j];
        }
        *(float4*)(out + off) = o;
        off += 1024;
    }
}

// ============================================================================
// Launch
// ============================================================================
extern "C" void kernel_launch(void* const* d_in, const int* in_sizes, int n_in,
                              void* d_out, int out_size) {
    const float* x  = (const float*)d_in[0];
    const float* Wg = (const float*)d_in[1];
    const float* bg = (const float*)d_in[2];
    const float* Wv = (const float*)d_in[3];
    const float* bv = (const float*)d_in[4];
    const float* Wd = (const float*)d_in[5];
    const float* bd = (const float*)d_in[6];
    float* out = (float*)d_out;
    (void)in_sizes; (void)n_in; (void)out_size;

    convert_kernel<<<CVT_F4 / 256, 256>>>(x, Wg, Wv, Wd);

    cudaFuncSetAttribute(gemm3_kernel,
                         cudaFuncAttributeMaxDynamicSharedMemorySize, GEMM_SMEM);
    gemm3_kernel<<<dim3(M_TOT / 256, D_DIM / 64), 512, GEMM_SMEM>>>(bg, bv, bd);

    scan_phase2<<<512, 256>>>();
    scan_apply<<<dim3(4, NCH), 256>>>(out);
}